// round 14
// baseline (speedup 1.0000x reference)
#include <cuda_runtime.h>
#include <cuda_fp16.h>
#include <cstdint>

#define CIN_   128
#define COUT_  256
#define KTOT_  1152
#define TI_    31          // tile rows
#define TJ_    31          // real tiles per row (padded to 32)
#define POS_   16

// scratch
#define U_ELEMS  ((size_t)64 * TI_ * POS_ * 32 * CIN_)    // 260 MB fp16
#define V_ELEMS  ((size_t)64 * POS_ * COUT_ * CIN_)       // 67 MB fp16
__device__ __half g_U[U_ELEMS];
__device__ __half g_V[V_ELEMS];

// main kernel smem
#define ROWB   288                       // bytes per 128-half row (padded)
#define USZ    (32 * ROWB)               // 9216
#define VSZ    (128 * ROWB)              // 36864
#define STAGE  (USZ + VSZ)               // 46080
#define BBS_OFF (2 * STAGE)              // 92160
#define SMEM_MAIN (BBS_OFF + 512)        // 92672

__device__ __forceinline__ uint32_t smem_u32(const void* p) {
    uint32_t a;
    asm("{ .reg .u64 t; cvta.to.shared.u64 t, %1; cvt.u32.u64 %0, t; }" : "=r"(a) : "l"(p));
    return a;
}
__device__ __forceinline__ void cp16(uint32_t dst, const void* src) {
    asm volatile("cp.async.cg.shared.global [%0], [%1], 16;"
                 :: "r"(dst), "l"(src) : "memory");
}
#define CP_COMMIT() asm volatile("cp.async.commit_group;" ::: "memory")
#define CP_WAIT0()  asm volatile("cp.async.wait_group 0;" ::: "memory")

__device__ __forceinline__ void mma_f16(float c[4],
                                        uint32_t a0, uint32_t a1, uint32_t a2, uint32_t a3,
                                        uint32_t b0, uint32_t b1) {
    asm volatile(
        "mma.sync.aligned.m16n8k16.row.col.f32.f16.f16.f32 "
        "{%0,%1,%2,%3}, {%4,%5,%6,%7}, {%8,%9}, {%0,%1,%2,%3};"
        : "+f"(c[0]), "+f"(c[1]), "+f"(c[2]), "+f"(c[3])
        : "r"(a0), "r"(a1), "r"(a2), "r"(a3), "r"(b0), "r"(b1));
}

// storage slot within a 16-chunk for original k (matches LDS.64 frag pattern)
__device__ __forceinline__ int kslot(int k) {
    return (k & 1) | (((k >> 3) & 1) << 1) | (((k >> 1) & 3) << 2);
}

// ---- U precompute: U = B^T d B per (b, tile, ci), fp16, interleaved
__global__ void __launch_bounds__(256, 2)
wino_u_kernel(const float* __restrict__ X)
{
    extern __shared__ char smc[];
    float* Xs = (float*)smc;                    // [4 r][64 w][32 ci] = 32 KB
    __half* Uo = (__half*)(smc + 32768);        // [16 pos][32 j][32 ci] = 32 KB

    const int t = threadIdx.x;
    const int i = blockIdx.x;
    const int b = blockIdx.y;
    const size_t ubase = ((size_t)(b * TI_ + i) * POS_) * (32 * CIN_);

    for (int cch = 0; cch < 4; cch++) {
        const int ci0 = cch * 32;
        __syncthreads();
        // load Xs
        #pragma unroll
        for (int u = 0; u < 8; u++) {
            int unit = t + 256 * u;
            int rw = unit >> 3, seg = unit & 7;
            int r = rw >> 6, w = rw & 63;
            float4 vv = *(const float4*)(X + (((size_t)(b * 64 + 2 * i + r)) * 64 + w) * CIN_
                                           + ci0 + seg * 4);
            *(float4*)&Xs[rw * 32 + seg * 4] = vv;
        }
        __syncthreads();
        // transform
        #pragma unroll
        for (int it = 0; it < 4; it++) {
            const int id = it * 256 + t;
            const int j = id >> 5, ciL = id & 31;
            float d[4][4];
            if (j < TJ_) {
                #pragma unroll
                for (int r = 0; r < 4; r++)
                    #pragma unroll
                    for (int s = 0; s < 4; s++)
                        d[r][s] = Xs[(r * 64 + 2 * j + s) * 32 + ciL];
            } else {
                #pragma unroll
                for (int r = 0; r < 4; r++)
                    #pragma unroll
                    for (int s = 0; s < 4; s++) d[r][s] = 0.0f;
            }
            float tr[4][4];
            #pragma unroll
            for (int s = 0; s < 4; s++) {
                tr[0][s] = d[0][s] - d[2][s];
                tr[1][s] = d[1][s] + d[2][s];
                tr[2][s] = d[2][s] - d[1][s];
                tr[3][s] = d[1][s] - d[3][s];
            }
            const int slotL = (ciL & 16) + kslot(ciL & 15);
            #pragma unroll
            for (int x = 0; x < 4; x++) {
                float u0 = tr[x][0] - tr[x][2];
                float u1 = tr[x][1] + tr[x][2];
                float u2 = tr[x][2] - tr[x][1];
                float u3 = tr[x][1] - tr[x][3];
                Uo[((x * 4 + 0) * 32 + j) * 32 + slotL] = __float2half_rn(u0);
                Uo[((x * 4 + 1) * 32 + j) * 32 + slotL] = __float2half_rn(u1);
                Uo[((x * 4 + 2) * 32 + j) * 32 + slotL] = __float2half_rn(u2);
                Uo[((x * 4 + 3) * 32 + j) * 32 + slotL] = __float2half_rn(u3);
            }
        }
        __syncthreads();
        // store
        #pragma unroll
        for (int u = 0; u < 2; u++) {
            int row = t + 256 * u;
            int pos = row >> 5, j = row & 31;
            const uint4* sp = (const uint4*)&Uo[(pos * 32 + j) * 32];
            uint4* dp = (uint4*)(g_U + ubase + (size_t)pos * (32 * CIN_) + j * CIN_ + ci0);
            dp[0] = sp[0]; dp[1] = sp[1]; dp[2] = sp[2]; dp[3] = sp[3];
        }
    }
}

// ---- V precompute: V = G (W*Werr) G^T per (b, ci, n), fp16, interleaved
__global__ void __launch_bounds__(256, 1)
wino_v_kernel(const float* __restrict__ W, const float* __restrict__ Werr)
{
    extern __shared__ char smc[];
    float* Ws = (float*)smc;                    // [144 khw*ci][64 n] 36864 B
    float* Es = (float*)(smc + 36864);
    __half* Vo = (__half*)(smc + 73728);        // [16 pos][64 n][16 slot] 32768 B

    const int t  = threadIdx.x;
    const int cc = blockIdx.x;        // ci chunk of 16
    const int nB = blockIdx.y;        // n block of 64
    const int b  = blockIdx.z;
    const int ci0 = cc * 16, n0 = nB * 64;
    const float* Eb = Werr + (size_t)b * ((size_t)KTOT_ * COUT_);

    #pragma unroll
    for (int u = 0; u < 9; u++) {
        int unit = t + 256 * u;
        int kc = unit >> 4, seg = unit & 15;
        int khw = kc >> 4, ci = kc & 15;      // 144 = 9*16
        size_t gi = (size_t)(khw * CIN_ + ci0 + ci) * COUT_ + n0 + seg * 4;
        *(float4*)&Ws[kc * 64 + seg * 4] = *(const float4*)(W + gi);
        *(float4*)&Es[kc * 64 + seg * 4] = *(const float4*)(Eb + gi);
    }
    __syncthreads();

    #pragma unroll
    for (int it = 0; it < 4; it++) {
        const int id = it * 256 + t;
        const int n = id & 63, ci = id >> 6;      // ci 0..15
        float gg[3][3];
        #pragma unroll
        for (int kh = 0; kh < 3; kh++)
            #pragma unroll
            for (int kw = 0; kw < 3; kw++) {
                int kc = (kh * 3 + kw) * 16 + ci;
                gg[kh][kw] = Ws[kc * 64 + n] * Es[kc * 64 + n];
            }
        float q[4][3];
        #pragma unroll
        for (int s = 0; s < 3; s++) {
            q[0][s] = gg[0][s];
            q[1][s] = 0.5f * (gg[0][s] + gg[1][s] + gg[2][s]);
            q[2][s] = 0.5f * (gg[0][s] - gg[1][s] + gg[2][s]);
            q[3][s] = gg[2][s];
        }
        const int sl = kslot(ci);
        #pragma unroll
        for (int x = 0; x < 4; x++) {
            float v0 = q[x][0];
            float v1 = 0.5f * (q[x][0] + q[x][1] + q[x][2]);
            float v2 = 0.5f * (q[x][0] - q[x][1] + q[x][2]);
            float v3 = q[x][2];
            Vo[((x * 4 + 0) * 64 + n) * 16 + sl] = __float2half_rn(v0);
            Vo[((x * 4 + 1) * 64 + n) * 16 + sl] = __float2half_rn(v1);
            Vo[((x * 4 + 2) * 64 + n) * 16 + sl] = __float2half_rn(v2);
            Vo[((x * 4 + 3) * 64 + n) * 16 + sl] = __float2half_rn(v3);
        }
    }
    __syncthreads();

    #pragma unroll
    for (int u = 0; u < 4; u++) {
        int row = t + 256 * u;
        int pos = row >> 6, n = row & 63;
        const uint4* sp = (const uint4*)&Vo[row * 16];
        uint4* dp = (uint4*)(g_V + ((size_t)(b * POS_ + pos) * COUT_ + n0 + n) * CIN_ + ci0);
        dp[0] = sp[0]; dp[1] = sp[1];
    }
}

// ---- Main: per (b, tile-row i, n-block): 16 pos GEMMs + inverse transform in regs
__global__ void __launch_bounds__(256, 1)
wino_main_kernel(const float* __restrict__ bias,
                 const float* __restrict__ Berr, float* __restrict__ out)
{
    extern __shared__ char smc[];
    const uint32_t sb = smem_u32(smc);
    float* const bbs = (float*)(smc + BBS_OFF);

    const int tid  = threadIdx.x;
    const int lane = tid & 31;
    const int wid  = tid >> 5;
    const int wm   = wid >> 2;        // 0..1 (M: 16 tiles)
    const int wn   = wid & 3;         // 0..3 (N: 32 cols)
    const int g    = lane >> 2;
    const int tq   = lane & 3;

    const int nb = blockIdx.x;        // 0..1
    const int i  = blockIdx.y;        // 0..30
    const int b  = blockIdx.z;

    if (tid < 128) bbs[tid] = bias[nb * 128 + tid] * Berr[b * COUT_ + nb * 128 + tid];

    const __half* Ub = g_U + ((size_t)(b * TI_ + i) * POS_) * (32 * CIN_);
    const __half* Vb = g_V + ((size_t)(b * POS_) * COUT_ + nb * 128) * CIN_;

    auto prefetch = [&](int pos, int s) {
        const __half* Up = Ub + (size_t)pos * (32 * CIN_);
        const __half* Vp = Vb + (size_t)pos * (COUT_ * CIN_);
        const uint32_t ust = sb + s * STAGE;
        #pragma unroll
        for (int u = 0; u < 2; u++) {
            int unit = tid + 256 * u;
            int row = unit >> 4, seg = unit & 15;
            cp16(ust + row * ROWB + seg * 16, Up + row * CIN_ + seg * 8);
        }
        const uint32_t vst = ust + USZ;
        #pragma unroll
        for (int u = 0; u < 8; u++) {
            int unit = tid + 256 * u;
            int row = unit >> 4, seg = unit & 15;
            cp16(vst + row * ROWB + seg * 16, Vp + row * CIN_ + seg * 8);
        }
    };

    float outacc[2][4][2][4];
    #pragma unroll
    for (int a0 = 0; a0 < 2; a0++)
        #pragma unroll
        for (int a1 = 0; a1 < 4; a1++)
            #pragma unroll
            for (int a2 = 0; a2 < 2; a2++)
                #pragma unroll
                for (int a3 = 0; a3 < 4; a3++) outacc[a0][a1][a2][a3] = 0.0f;

    prefetch(0, 0);
    CP_COMMIT();

    const int urow = (wm * 16 + g) * ROWB + 8 * tq;

    #pragma unroll 1
    for (int pos = 0; pos < POS_; pos++) {
        CP_WAIT0();
        __syncthreads();
        if (pos + 1 < POS_) { prefetch(pos + 1, (pos + 1) & 1); CP_COMMIT(); }

        const char* Us = smc + (pos & 1) * STAGE;
        const char* Vs = Us + USZ;

        float macc[4][4];
        #pragma unroll
        for (int nf = 0; nf < 4; nf++)
            #pragma unroll
            for (int q = 0; q < 4; q++) macc[nf][q] = 0.0f;

        #pragma unroll
        for (int c = 0; c < 8; c++) {
            uint2 ua = *(const uint2*)(Us + urow + c * 32);
            uint2 u8 = *(const uint2*)(Us + urow + 8 * ROWB + c * 32);
            #pragma unroll
            for (int nf = 0; nf < 4; nf++) {
                const int nrow = wn * 32 + nf * 8 + g;
                uint2 vv = *(const uint2*)(Vs + nrow * ROWB + 8 * tq + c * 32);
                mma_f16(macc[nf], ua.x, u8.x, ua.y, u8.y, vv.x, vv.y);
            }
        }

        // fold M into outputs with A^T coefficients
        const int x = pos >> 2, y = pos & 3;
        const float ax0 = (x == 3) ? 0.f : 1.f;
        const float ax1 = (x == 0) ? 0.f : ((x == 1) ? 1.f : -1.f);
        const float ay0 = (y == 3) ? 0.f : 1.f;
        const float ay1 = (y == 0) ? 0.f : ((y == 1) ? 1.f : -1.f);
        const float c00 = ax0 * ay0, c01 = ax0 * ay1;
        const float c10 = ax1 * ay0, c11 = ax1 * ay1;
        #pragma unroll
        for (int nf = 0; nf < 4; nf++)
            #pragma unroll
            for (int col = 0; col < 2; col++) {
                float m0 = macc[nf][col];          // tile row g
                float m1 = macc[nf][2 + col];      // tile row g+8
                outacc[0][nf][col][0] += c00 * m0;
                outacc[0][nf][col][1] += c01 * m0;
                outacc[0][nf][col][2] += c10 * m0;
                outacc[0][nf][col][3] += c11 * m0;
                outacc[1][nf][col][0] += c00 * m1;
                outacc[1][nf][col][1] += c01 * m1;
                outacc[1][nf][col][2] += c10 * m1;
                outacc[1][nf][col][3] += c11 * m1;
            }
    }

    // ---- Epilogue: inverse-transformed outputs + bias -> out
    #pragma unroll
    for (int mrh = 0; mrh < 2; mrh++) {
        const int j = wm * 16 + g + 8 * mrh;
        if (j < TJ_) {
            #pragma unroll
            for (int p = 0; p < 2; p++) {
                const int ho = 2 * i + p;
                #pragma unroll
                for (int q = 0; q < 2; q++) {
                    const int wo = 2 * j + q;
                    float* op = out + (((size_t)b * 62 + ho) * 62 + wo) * COUT_
                                   + nb * 128 + wn * 32 + 2 * tq;
                    #pragma unroll
                    for (int nf = 0; nf < 4; nf++) {
                        float2 bb = *(const float2*)&bbs[wn * 32 + nf * 8 + 2 * tq];
                        float2 v;
                        v.x = outacc[mrh][nf][0][p * 2 + q] + bb.x;
                        v.y = outacc[mrh][nf][1][p * 2 + q] + bb.y;
                        *(float2*)(op + nf * 8) = v;
                    }
                }
            }
        }
    }
}

extern "C" void kernel_launch(void* const* d_in, const int* in_sizes, int n_in,
                              void* d_out, int out_size)
{
    const float* X    = (const float*)d_in[0];
    const float* W    = (const float*)d_in[1];
    const float* bias = (const float*)d_in[2];
    const float* Werr = (const float*)d_in[3];
    const float* Berr = (const float*)d_in[4];
    float* out = (float*)d_out;

    cudaFuncSetAttribute(wino_u_kernel,
                         cudaFuncAttributeMaxDynamicSharedMemorySize, 65536);
    cudaFuncSetAttribute(wino_v_kernel,
                         cudaFuncAttributeMaxDynamicSharedMemorySize, 106496);
    cudaFuncSetAttribute(wino_main_kernel,
                         cudaFuncAttributeMaxDynamicSharedMemorySize, SMEM_MAIN);

    wino_u_kernel<<<dim3(TI_, 64), 256, 65536>>>(X);
    wino_v_kernel<<<dim3(8, 4, 64), 256, 106496>>>(W, Werr);
    wino_main_kernel<<<dim3(2, TI_, 64), 256, SMEM_MAIN>>>(bias, Berr, out);
}

// round 15
// speedup vs baseline: 1.0997x; 1.0997x over previous
#include <cuda_runtime.h>
#include <cuda_fp16.h>
#include <cstdint>

#define CIN_   128
#define COUT_  256
#define KTOT_  1152
#define TI_    31          // tile rows
#define TJ_    31          // real tiles per row (padded to 32)
#define POS_   16

// scratch
#define U_ELEMS  ((size_t)64 * TI_ * POS_ * 32 * CIN_)    // 260 MB fp16
#define V_ELEMS  ((size_t)64 * POS_ * COUT_ * CIN_)       // 67 MB fp16
__device__ __half g_U[U_ELEMS];   // [b][i][pos][cch][j][32ci-slots]
__device__ __half g_V[V_ELEMS];   // [b][pos][n][ci-slots]

// main kernel smem
#define ROWB   288                       // bytes per 128-half row (padded)
#define USZ    (32 * ROWB)               // 9216
#define VSZ    (128 * ROWB)              // 36864
#define STAGE  (USZ + VSZ)               // 46080
#define BBS_OFF (2 * STAGE)              // 92160
#define SMEM_MAIN (BBS_OFF + 512)        // 92672

__device__ __forceinline__ uint32_t smem_u32(const void* p) {
    uint32_t a;
    asm("{ .reg .u64 t; cvta.to.shared.u64 t, %1; cvt.u32.u64 %0, t; }" : "=r"(a) : "l"(p));
    return a;
}
__device__ __forceinline__ void cp16(uint32_t dst, const void* src) {
    asm volatile("cp.async.cg.shared.global [%0], [%1], 16;"
                 :: "r"(dst), "l"(src) : "memory");
}
#define CP_COMMIT() asm volatile("cp.async.commit_group;" ::: "memory")
#define CP_WAIT0()  asm volatile("cp.async.wait_group 0;" ::: "memory")

__device__ __forceinline__ void mma_f16(float c[4],
                                        uint32_t a0, uint32_t a1, uint32_t a2, uint32_t a3,
                                        uint32_t b0, uint32_t b1) {
    asm volatile(
        "mma.sync.aligned.m16n8k16.row.col.f32.f16.f16.f32 "
        "{%0,%1,%2,%3}, {%4,%5,%6,%7}, {%8,%9}, {%0,%1,%2,%3};"
        : "+f"(c[0]), "+f"(c[1]), "+f"(c[2]), "+f"(c[3])
        : "r"(a0), "r"(a1), "r"(a2), "r"(a3), "r"(b0), "r"(b1));
}

// storage slot within a 16-chunk for original k (matches LDS.64 frag pattern)
__device__ __forceinline__ int kslot(int k) {
    return (k & 1) | (((k >> 3) & 1) << 1) | (((k >> 1) & 3) << 2);
}

// ---- U precompute: U = B^T d B per (b, tile, ci), fp16, interleaved
// grid (TI_, 4 cch, 64 b); g_U layout per (b,i): [16 pos][4 cch][32 j][32 ci-slots]
__global__ void __launch_bounds__(256, 3)
wino_u_kernel(const float* __restrict__ X)
{
    extern __shared__ char smc[];
    float* Xs = (float*)smc;                    // [4 r][64 w][32 ci] = 32 KB
    __half* Uo = (__half*)(smc + 32768);        // [16 pos][32 j][32 slots] = 32 KB

    const int t   = threadIdx.x;
    const int i   = blockIdx.x;
    const int cch = blockIdx.y;
    const int b   = blockIdx.z;
    const int ci0 = cch * 32;
    const size_t ubase = (size_t)(b * TI_ + i) * 65536;   // halfs per (b,i)

    // load Xs: 2048 float4 units
    #pragma unroll
    for (int u = 0; u < 8; u++) {
        int unit = t + 256 * u;
        int rw = unit >> 3, seg = unit & 7;
        int r = rw >> 6, w = rw & 63;
        float4 vv = *(const float4*)(X + (((size_t)(b * 64 + 2 * i + r)) * 64 + w) * CIN_
                                       + ci0 + seg * 4);
        *(float4*)&Xs[rw * 32 + seg * 4] = vv;
    }
    __syncthreads();

    // transform: 1024 (j, ciL) units
    #pragma unroll
    for (int it = 0; it < 4; it++) {
        const int id = it * 256 + t;
        const int j = id >> 5, ciL = id & 31;
        float d[4][4];
        if (j < TJ_) {
            #pragma unroll
            for (int r = 0; r < 4; r++)
                #pragma unroll
                for (int s = 0; s < 4; s++)
                    d[r][s] = Xs[(r * 64 + 2 * j + s) * 32 + ciL];
        } else {
            #pragma unroll
            for (int r = 0; r < 4; r++)
                #pragma unroll
                for (int s = 0; s < 4; s++) d[r][s] = 0.0f;
        }
        float tr[4][4];
        #pragma unroll
        for (int s = 0; s < 4; s++) {
            tr[0][s] = d[0][s] - d[2][s];
            tr[1][s] = d[1][s] + d[2][s];
            tr[2][s] = d[2][s] - d[1][s];
            tr[3][s] = d[1][s] - d[3][s];
        }
        const int slotL = (ciL & 16) + kslot(ciL & 15);
        #pragma unroll
        for (int x = 0; x < 4; x++) {
            float u0 = tr[x][0] - tr[x][2];
            float u1 = tr[x][1] + tr[x][2];
            float u2 = tr[x][2] - tr[x][1];
            float u3 = tr[x][1] - tr[x][3];
            Uo[((x * 4 + 0) * 32 + j) * 32 + slotL] = __float2half_rn(u0);
            Uo[((x * 4 + 1) * 32 + j) * 32 + slotL] = __float2half_rn(u1);
            Uo[((x * 4 + 2) * 32 + j) * 32 + slotL] = __float2half_rn(u2);
            Uo[((x * 4 + 3) * 32 + j) * 32 + slotL] = __float2half_rn(u3);
        }
    }
    __syncthreads();

    // store: fully coalesced; per (pos): 2 KB contiguous in g_U
    #pragma unroll
    for (int u = 0; u < 8; u++) {
        int unit = t + 256 * u;
        int row = unit >> 2, seg = unit & 3;      // row = pos*32 + j
        int pos = row >> 5, j = row & 31;
        uint4 v = *(const uint4*)&Uo[row * 32 + seg * 8];
        *(uint4*)(g_U + ubase + (size_t)pos * 4096 + cch * 1024 + j * 32 + seg * 8) = v;
    }
}

// ---- V precompute: V = G (W*Werr) G^T per (b, ci, n), fp16, interleaved
__global__ void __launch_bounds__(256, 1)
wino_v_kernel(const float* __restrict__ W, const float* __restrict__ Werr)
{
    extern __shared__ char smc[];
    float* Ws = (float*)smc;                    // [144 khw*ci][64 n] 36864 B
    float* Es = (float*)(smc + 36864);
    __half* Vo = (__half*)(smc + 73728);        // [16 pos][64 n][16 slot] 32768 B

    const int t  = threadIdx.x;
    const int cc = blockIdx.x;        // ci chunk of 16
    const int nB = blockIdx.y;        // n block of 64
    const int b  = blockIdx.z;
    const int ci0 = cc * 16, n0 = nB * 64;
    const float* Eb = Werr + (size_t)b * ((size_t)KTOT_ * COUT_);

    #pragma unroll
    for (int u = 0; u < 9; u++) {
        int unit = t + 256 * u;
        int kc = unit >> 4, seg = unit & 15;
        int khw = kc >> 4, ci = kc & 15;      // 144 = 9*16
        size_t gi = (size_t)(khw * CIN_ + ci0 + ci) * COUT_ + n0 + seg * 4;
        *(float4*)&Ws[kc * 64 + seg * 4] = *(const float4*)(W + gi);
        *(float4*)&Es[kc * 64 + seg * 4] = *(const float4*)(Eb + gi);
    }
    __syncthreads();

    #pragma unroll
    for (int it = 0; it < 4; it++) {
        const int id = it * 256 + t;
        const int n = id & 63, ci = id >> 6;      // ci 0..15
        float gg[3][3];
        #pragma unroll
        for (int kh = 0; kh < 3; kh++)
            #pragma unroll
            for (int kw = 0; kw < 3; kw++) {
                int kc = (kh * 3 + kw) * 16 + ci;
                gg[kh][kw] = Ws[kc * 64 + n] * Es[kc * 64 + n];
            }
        float q[4][3];
        #pragma unroll
        for (int s = 0; s < 3; s++) {
            q[0][s] = gg[0][s];
            q[1][s] = 0.5f * (gg[0][s] + gg[1][s] + gg[2][s]);
            q[2][s] = 0.5f * (gg[0][s] - gg[1][s] + gg[2][s]);
            q[3][s] = gg[2][s];
        }
        const int sl = kslot(ci);
        #pragma unroll
        for (int x = 0; x < 4; x++) {
            float v0 = q[x][0];
            float v1 = 0.5f * (q[x][0] + q[x][1] + q[x][2]);
            float v2 = 0.5f * (q[x][0] - q[x][1] + q[x][2]);
            float v3 = q[x][2];
            Vo[((x * 4 + 0) * 64 + n) * 16 + sl] = __float2half_rn(v0);
            Vo[((x * 4 + 1) * 64 + n) * 16 + sl] = __float2half_rn(v1);
            Vo[((x * 4 + 2) * 64 + n) * 16 + sl] = __float2half_rn(v2);
            Vo[((x * 4 + 3) * 64 + n) * 16 + sl] = __float2half_rn(v3);
        }
    }
    __syncthreads();

    #pragma unroll
    for (int u = 0; u < 4; u++) {
        int row = t + 256 * u;
        int pos = row >> 6, n = row & 63;
        const uint4* sp = (const uint4*)&Vo[row * 16];
        uint4* dp = (uint4*)(g_V + ((size_t)(b * POS_ + pos) * COUT_ + n0 + n) * CIN_ + ci0);
        dp[0] = sp[0]; dp[1] = sp[1];
    }
}

// ---- Main: per (b, tile-row i, n-block): 16 pos GEMMs + inverse transform in regs
__global__ void __launch_bounds__(256, 1)
wino_main_kernel(const float* __restrict__ bias,
                 const float* __restrict__ Berr, float* __restrict__ out)
{
    extern __shared__ char smc[];
    const uint32_t sb = smem_u32(smc);
    float* const bbs = (float*)(smc + BBS_OFF);

    const int tid  = threadIdx.x;
    const int lane = tid & 31;
    const int wid  = tid >> 5;
    const int wm   = wid >> 2;        // 0..1 (M: 16 tiles)
    const int wn   = wid & 3;         // 0..3 (N: 32 cols)
    const int g    = lane >> 2;
    const int tq   = lane & 3;

    const int nb = blockIdx.x;        // 0..1
    const int i  = blockIdx.y;        // 0..30
    const int b  = blockIdx.z;

    if (tid < 128) bbs[tid] = bias[nb * 128 + tid] * Berr[b * COUT_ + nb * 128 + tid];

    const __half* Ub = g_U + (size_t)(b * TI_ + i) * 65536;
    const __half* Vb = g_V + ((size_t)(b * POS_) * COUT_ + nb * 128) * CIN_;

    auto prefetch = [&](int pos, int s) {
        const __half* Up = Ub + (size_t)pos * 4096;
        const __half* Vp = Vb + (size_t)pos * (COUT_ * CIN_);
        const uint32_t ust = sb + s * STAGE;
        #pragma unroll
        for (int u = 0; u < 2; u++) {
            int unit = tid + 256 * u;
            int j = unit >> 4, cs = unit & 15;    // cch = cs>>2, seg = cs&3
            cp16(ust + j * ROWB + cs * 16,
                 Up + (cs >> 2) * 1024 + j * 32 + (cs & 3) * 8);
        }
        const uint32_t vst = ust + USZ;
        #pragma unroll
        for (int u = 0; u < 8; u++) {
            int unit = tid + 256 * u;
            int row = unit >> 4, seg = unit & 15;
            cp16(vst + row * ROWB + seg * 16, Vp + row * CIN_ + seg * 8);
        }
    };

    float outacc[2][4][2][4];
    #pragma unroll
    for (int a0 = 0; a0 < 2; a0++)
        #pragma unroll
        for (int a1 = 0; a1 < 4; a1++)
            #pragma unroll
            for (int a2 = 0; a2 < 2; a2++)
                #pragma unroll
                for (int a3 = 0; a3 < 4; a3++) outacc[a0][a1][a2][a3] = 0.0f;

    prefetch(0, 0);
    CP_COMMIT();

    const int urow = (wm * 16 + g) * ROWB + 8 * tq;
    const int vcol = 8 * tq;

    #pragma unroll 1
    for (int pos = 0; pos < POS_; pos++) {
        CP_WAIT0();
        __syncthreads();
        if (pos + 1 < POS_) { prefetch(pos + 1, (pos + 1) & 1); CP_COMMIT(); }

        const char* Us = smc + (pos & 1) * STAGE;
        const char* Vs = Us + USZ;

        float macc[4][4];
        #pragma unroll
        for (int nf = 0; nf < 4; nf++)
            #pragma unroll
            for (int q = 0; q < 4; q++) macc[nf][q] = 0.0f;

        // c-chunk pipelined fragment loads
        uint2 ua[2], u8[2], vv[2][4];
        {
            ua[0] = *(const uint2*)(Us + urow);
            u8[0] = *(const uint2*)(Us + urow + 8 * ROWB);
            #pragma unroll
            for (int nf = 0; nf < 4; nf++)
                vv[0][nf] = *(const uint2*)(Vs + (wn * 32 + nf * 8 + g) * ROWB + vcol);
        }
        #pragma unroll
        for (int c = 0; c < 8; c++) {
            const int cur = c & 1, nxt = cur ^ 1;
            if (c < 7) {
                ua[nxt] = *(const uint2*)(Us + urow + (c + 1) * 32);
                u8[nxt] = *(const uint2*)(Us + urow + 8 * ROWB + (c + 1) * 32);
                #pragma unroll
                for (int nf = 0; nf < 4; nf++)
                    vv[nxt][nf] = *(const uint2*)(Vs + (wn * 32 + nf * 8 + g) * ROWB
                                                  + vcol + (c + 1) * 32);
            }
            #pragma unroll
            for (int nf = 0; nf < 4; nf++)
                mma_f16(macc[nf], ua[cur].x, u8[cur].x, ua[cur].y, u8[cur].y,
                        vv[cur][nf].x, vv[cur][nf].y);
        }

        // fold M into outputs with A^T coefficients
        const int x = pos >> 2, y = pos & 3;
        const float ax0 = (x == 3) ? 0.f : 1.f;
        const float ax1 = (x == 0) ? 0.f : ((x == 1) ? 1.f : -1.f);
        const float ay0 = (y == 3) ? 0.f : 1.f;
        const float ay1 = (y == 0) ? 0.f : ((y == 1) ? 1.f : -1.f);
        const float c00 = ax0 * ay0, c01 = ax0 * ay1;
        const float c10 = ax1 * ay0, c11 = ax1 * ay1;
        #pragma unroll
        for (int nf = 0; nf < 4; nf++)
            #pragma unroll
            for (int col = 0; col < 2; col++) {
                float m0 = macc[nf][col];          // tile row g
                float m1 = macc[nf][2 + col];      // tile row g+8
                outacc[0][nf][col][0] += c00 * m0;
                outacc[0][nf][col][1] += c01 * m0;
                outacc[0][nf][col][2] += c10 * m0;
                outacc[0][nf][col][3] += c11 * m0;
                outacc[1][nf][col][0] += c00 * m1;
                outacc[1][nf][col][1] += c01 * m1;
                outacc[1][nf][col][2] += c10 * m1;
                outacc[1][nf][col][3] += c11 * m1;
            }
    }

    // ---- Epilogue: inverse-transformed outputs + bias -> out
    #pragma unroll
    for (int mrh = 0; mrh < 2; mrh++) {
        const int j = wm * 16 + g + 8 * mrh;
        if (j < TJ_) {
            #pragma unroll
            for (int p = 0; p < 2; p++) {
                const int ho = 2 * i + p;
                #pragma unroll
                for (int q = 0; q < 2; q++) {
                    const int wo = 2 * j + q;
                    float* op = out + (((size_t)b * 62 + ho) * 62 + wo) * COUT_
                                   + nb * 128 + wn * 32 + 2 * tq;
                    #pragma unroll
                    for (int nf = 0; nf < 4; nf++) {
                        float2 bb = *(const float2*)&bbs[wn * 32 + nf * 8 + 2 * tq];
                        float2 v;
                        v.x = outacc[mrh][nf][0][p * 2 + q] + bb.x;
                        v.y = outacc[mrh][nf][1][p * 2 + q] + bb.y;
                        *(float2*)(op + nf * 8) = v;
                    }
                }
            }
        }
    }
}

extern "C" void kernel_launch(void* const* d_in, const int* in_sizes, int n_in,
                              void* d_out, int out_size)
{
    const float* X    = (const float*)d_in[0];
    const float* W    = (const float*)d_in[1];
    const float* bias = (const float*)d_in[2];
    const float* Werr = (const float*)d_in[3];
    const float* Berr = (const float*)d_in[4];
    float* out = (float*)d_out;

    cudaFuncSetAttribute(wino_u_kernel,
                         cudaFuncAttributeMaxDynamicSharedMemorySize, 65536);
    cudaFuncSetAttribute(wino_v_kernel,
                         cudaFuncAttributeMaxDynamicSharedMemorySize, 106496);
    cudaFuncSetAttribute(wino_main_kernel,
                         cudaFuncAttributeMaxDynamicSharedMemorySize, SMEM_MAIN);

    wino_u_kernel<<<dim3(TI_, 4, 64), 256, 65536>>>(X);
    wino_v_kernel<<<dim3(8, 4, 64), 256, 106496>>>(W, Werr);
    wino_main_kernel<<<dim3(2, TI_, 64), 256, SMEM_MAIN>>>(bias, Berr, out);
}

// round 16
// speedup vs baseline: 1.3484x; 1.2261x over previous
#include <cuda_runtime.h>
#include <cuda_fp16.h>
#include <cstdint>

#define CIN_   128
#define COUT_  256
#define KTOT_  1152
#define TI_    31          // real tile rows (padded to 32 in g_U)
#define TJ_    31          // real tiles per row (padded to 32)
#define POS_   16

// scratch
#define U_ELEMS  ((size_t)64 * 32 * POS_ * 32 * CIN_)     // 268 MB fp16 (32 i-rows, row 31 stays zero)
#define V_ELEMS  ((size_t)64 * POS_ * COUT_ * CIN_)       // 67 MB fp16
__device__ __half g_U[U_ELEMS];   // [b][i(32)][pos][cch][j][32ci-slots]
__device__ __half g_V[V_ELEMS];   // [b][pos][n][ci-slots]

// main kernel smem
#define ROWB   288                       // bytes per 128-half row (padded)
#define USZ    (64 * ROWB)               // 18432
#define VSZ    (128 * ROWB)              // 36864
#define STAGE  (USZ + VSZ)               // 55296
#define BBS_OFF (2 * STAGE)              // 110592
#define SMEM_MAIN (BBS_OFF + 512)        // 111104

__device__ __forceinline__ uint32_t smem_u32(const void* p) {
    uint32_t a;
    asm("{ .reg .u64 t; cvta.to.shared.u64 t, %1; cvt.u32.u64 %0, t; }" : "=r"(a) : "l"(p));
    return a;
}
__device__ __forceinline__ void cp16(uint32_t dst, const void* src) {
    asm volatile("cp.async.cg.shared.global [%0], [%1], 16;"
                 :: "r"(dst), "l"(src) : "memory");
}
#define CP_COMMIT() asm volatile("cp.async.commit_group;" ::: "memory")
#define CP_WAIT0()  asm volatile("cp.async.wait_group 0;" ::: "memory")

__device__ __forceinline__ void mma_f16(float c[4],
                                        uint32_t a0, uint32_t a1, uint32_t a2, uint32_t a3,
                                        uint32_t b0, uint32_t b1) {
    asm volatile(
        "mma.sync.aligned.m16n8k16.row.col.f32.f16.f16.f32 "
        "{%0,%1,%2,%3}, {%4,%5,%6,%7}, {%8,%9}, {%0,%1,%2,%3};"
        : "+f"(c[0]), "+f"(c[1]), "+f"(c[2]), "+f"(c[3])
        : "r"(a0), "r"(a1), "r"(a2), "r"(a3), "r"(b0), "r"(b1));
}

__device__ __forceinline__ int kslot(int k) {
    return (k & 1) | (((k >> 3) & 1) << 1) | (((k >> 1) & 3) << 2);
}

// ---- U precompute (unchanged math; g_U padded to 32 i-rows per b)
__global__ void __launch_bounds__(256, 3)
wino_u_kernel(const float* __restrict__ X)
{
    extern __shared__ char smc[];
    float* Xs = (float*)smc;                    // [4 r][64 w][32 ci] = 32 KB
    __half* Uo = (__half*)(smc + 32768);        // [16 pos][32 j][32 slots] = 32 KB

    const int t   = threadIdx.x;
    const int i   = blockIdx.x;
    const int cch = blockIdx.y;
    const int b   = blockIdx.z;
    const int ci0 = cch * 32;
    const size_t ubase = (size_t)(b * 32 + i) * 65536;

    #pragma unroll
    for (int u = 0; u < 8; u++) {
        int unit = t + 256 * u;
        int rw = unit >> 3, seg = unit & 7;
        int r = rw >> 6, w = rw & 63;
        float4 vv = *(const float4*)(X + (((size_t)(b * 64 + 2 * i + r)) * 64 + w) * CIN_
                                       + ci0 + seg * 4);
        *(float4*)&Xs[rw * 32 + seg * 4] = vv;
    }
    __syncthreads();

    #pragma unroll
    for (int it = 0; it < 4; it++) {
        const int id = it * 256 + t;
        const int j = id >> 5, ciL = id & 31;
        float d[4][4];
        if (j < TJ_) {
            #pragma unroll
            for (int r = 0; r < 4; r++)
                #pragma unroll
                for (int s = 0; s < 4; s++)
                    d[r][s] = Xs[(r * 64 + 2 * j + s) * 32 + ciL];
        } else {
            #pragma unroll
            for (int r = 0; r < 4; r++)
                #pragma unroll
                for (int s = 0; s < 4; s++) d[r][s] = 0.0f;
        }
        float tr[4][4];
        #pragma unroll
        for (int s = 0; s < 4; s++) {
            tr[0][s] = d[0][s] - d[2][s];
            tr[1][s] = d[1][s] + d[2][s];
            tr[2][s] = d[2][s] - d[1][s];
            tr[3][s] = d[1][s] - d[3][s];
        }
        const int slotL = (ciL & 16) + kslot(ciL & 15);
        #pragma unroll
        for (int x = 0; x < 4; x++) {
            float u0 = tr[x][0] - tr[x][2];
            float u1 = tr[x][1] + tr[x][2];
            float u2 = tr[x][2] - tr[x][1];
            float u3 = tr[x][1] - tr[x][3];
            Uo[((x * 4 + 0) * 32 + j) * 32 + slotL] = __float2half_rn(u0);
            Uo[((x * 4 + 1) * 32 + j) * 32 + slotL] = __float2half_rn(u1);
            Uo[((x * 4 + 2) * 32 + j) * 32 + slotL] = __float2half_rn(u2);
            Uo[((x * 4 + 3) * 32 + j) * 32 + slotL] = __float2half_rn(u3);
        }
    }
    __syncthreads();

    #pragma unroll
    for (int u = 0; u < 8; u++) {
        int unit = t + 256 * u;
        int row = unit >> 2, seg = unit & 3;
        int pos = row >> 5, j = row & 31;
        uint4 v = *(const uint4*)&Uo[row * 32 + seg * 8];
        *(uint4*)(g_U + ubase + (size_t)pos * 4096 + cch * 1024 + j * 32 + seg * 8) = v;
    }
}

// ---- V precompute (unchanged)
__global__ void __launch_bounds__(256, 1)
wino_v_kernel(const float* __restrict__ W, const float* __restrict__ Werr)
{
    extern __shared__ char smc[];
    float* Ws = (float*)smc;
    float* Es = (float*)(smc + 36864);
    __half* Vo = (__half*)(smc + 73728);

    const int t  = threadIdx.x;
    const int cc = blockIdx.x;
    const int nB = blockIdx.y;
    const int b  = blockIdx.z;
    const int ci0 = cc * 16, n0 = nB * 64;
    const float* Eb = Werr + (size_t)b * ((size_t)KTOT_ * COUT_);

    #pragma unroll
    for (int u = 0; u < 9; u++) {
        int unit = t + 256 * u;
        int kc = unit >> 4, seg = unit & 15;
        int khw = kc >> 4, ci = kc & 15;
        size_t gi = (size_t)(khw * CIN_ + ci0 + ci) * COUT_ + n0 + seg * 4;
        *(float4*)&Ws[kc * 64 + seg * 4] = *(const float4*)(W + gi);
        *(float4*)&Es[kc * 64 + seg * 4] = *(const float4*)(Eb + gi);
    }
    __syncthreads();

    #pragma unroll
    for (int it = 0; it < 4; it++) {
        const int id = it * 256 + t;
        const int n = id & 63, ci = id >> 6;
        float gg[3][3];
        #pragma unroll
        for (int kh = 0; kh < 3; kh++)
            #pragma unroll
            for (int kw = 0; kw < 3; kw++) {
                int kc = (kh * 3 + kw) * 16 + ci;
                gg[kh][kw] = Ws[kc * 64 + n] * Es[kc * 64 + n];
            }
        float q[4][3];
        #pragma unroll
        for (int s = 0; s < 3; s++) {
            q[0][s] = gg[0][s];
            q[1][s] = 0.5f * (gg[0][s] + gg[1][s] + gg[2][s]);
            q[2][s] = 0.5f * (gg[0][s] - gg[1][s] + gg[2][s]);
            q[3][s] = gg[2][s];
        }
        const int sl = kslot(ci);
        #pragma unroll
        for (int x = 0; x < 4; x++) {
            float v0 = q[x][0];
            float v1 = 0.5f * (q[x][0] + q[x][1] + q[x][2]);
            float v2 = 0.5f * (q[x][0] - q[x][1] + q[x][2]);
            float v3 = q[x][2];
            Vo[((x * 4 + 0) * 64 + n) * 16 + sl] = __float2half_rn(v0);
            Vo[((x * 4 + 1) * 64 + n) * 16 + sl] = __float2half_rn(v1);
            Vo[((x * 4 + 2) * 64 + n) * 16 + sl] = __float2half_rn(v2);
            Vo[((x * 4 + 3) * 64 + n) * 16 + sl] = __float2half_rn(v3);
        }
    }
    __syncthreads();

    #pragma unroll
    for (int u = 0; u < 4; u++) {
        int row = t + 256 * u;
        int pos = row >> 6, n = row & 63;
        const uint4* sp = (const uint4*)&Vo[row * 16];
        uint4* dp = (uint4*)(g_V + ((size_t)(b * POS_ + pos) * COUT_ + n0 + n) * CIN_ + ci0);
        dp[0] = sp[0]; dp[1] = sp[1];
    }
}

// ---- Main: per (nb, i-group of 2, b): M=64 tiles x N=128, 16 pos GEMMs
__global__ void __launch_bounds__(256, 1)
wino_main_kernel(const float* __restrict__ bias,
                 const float* __restrict__ Berr, float* __restrict__ out)
{
    extern __shared__ char smc[];
    const uint32_t sb = smem_u32(smc);
    float* const bbs = (float*)(smc + BBS_OFF);

    const int tid  = threadIdx.x;
    const int lane = tid & 31;
    const int wid  = tid >> 5;
    const int wm   = wid >> 1;        // 0..3 (M: 16 tiles each)
    const int wn   = wid & 1;         // 0..1 (N: 64 cols each)
    const int g    = lane >> 2;
    const int tq   = lane & 3;

    const int nb = blockIdx.x;        // 0..1
    const int ig = blockIdx.y;        // 0..15 (i-rows 2ig, 2ig+1)
    const int b  = blockIdx.z;

    if (tid < 128) bbs[tid] = bias[nb * 128 + tid] * Berr[b * COUT_ + nb * 128 + tid];

    const __half* Ub = g_U + (size_t)(b * 32 + 2 * ig) * 65536;
    const __half* Vb = g_V + ((size_t)(b * POS_) * COUT_ + nb * 128) * CIN_;

    auto prefetch = [&](int pos, int s) {
        const uint32_t ust = sb + s * STAGE;
        #pragma unroll
        for (int u = 0; u < 4; u++) {
            int unit = tid + 256 * u;
            int row = unit >> 4, cs = unit & 15;
            const __half* src = Ub + (size_t)(row >> 5) * 65536 + (size_t)pos * 4096
                                + (cs >> 2) * 1024 + (row & 31) * 32 + (cs & 3) * 8;
            cp16(ust + row * ROWB + cs * 16, src);
        }
        const uint32_t vst = ust + USZ;
        const __half* Vp = Vb + (size_t)pos * (COUT_ * CIN_);
        #pragma unroll
        for (int u = 0; u < 8; u++) {
            int unit = tid + 256 * u;
            int row = unit >> 4, seg = unit & 15;
            cp16(vst + row * ROWB + seg * 16, Vp + row * CIN_ + seg * 8);
        }
    };

    float outacc[2][8][2][4];
    #pragma unroll
    for (int a0 = 0; a0 < 2; a0++)
        #pragma unroll
        for (int a1 = 0; a1 < 8; a1++)
            #pragma unroll
            for (int a2 = 0; a2 < 2; a2++)
                #pragma unroll
                for (int a3 = 0; a3 < 4; a3++) outacc[a0][a1][a2][a3] = 0.0f;

    prefetch(0, 0);
    CP_COMMIT();

    const int urow0 = (wm * 16 + g) * ROWB + 8 * tq;
    const int vrow0 = (wn * 64 + g) * ROWB + 8 * tq;

    #pragma unroll 1
    for (int pos = 0; pos < POS_; pos++) {
        CP_WAIT0();
        __syncthreads();
        if (pos + 1 < POS_) { prefetch(pos + 1, (pos + 1) & 1); CP_COMMIT(); }

        const char* Us = smc + (pos & 1) * STAGE;
        const char* Vs = Us + USZ;

        float macc[8][4];
        #pragma unroll
        for (int nf = 0; nf < 8; nf++)
            #pragma unroll
            for (int q = 0; q < 4; q++) macc[nf][q] = 0.0f;

        #pragma unroll
        for (int c = 0; c < 8; c++) {
            uint2 ua = *(const uint2*)(Us + urow0 + c * 32);
            uint2 u8 = *(const uint2*)(Us + urow0 + 8 * ROWB + c * 32);
            #pragma unroll
            for (int nf = 0; nf < 8; nf++) {
                uint2 vv = *(const uint2*)(Vs + vrow0 + nf * 8 * ROWB + c * 32);
                mma_f16(macc[nf], ua.x, u8.x, ua.y, u8.y, vv.x, vv.y);
            }
        }

        const int x = pos >> 2, y = pos & 3;
        const float ax0 = (x == 3) ? 0.f : 1.f;
        const float ax1 = (x == 0) ? 0.f : ((x == 1) ? 1.f : -1.f);
        const float ay0 = (y == 3) ? 0.f : 1.f;
        const float ay1 = (y == 0) ? 0.f : ((y == 1) ? 1.f : -1.f);
        const float c00 = ax0 * ay0, c01 = ax0 * ay1;
        const float c10 = ax1 * ay0, c11 = ax1 * ay1;
        #pragma unroll
        for (int nf = 0; nf < 8; nf++)
            #pragma unroll
            for (int col = 0; col < 2; col++) {
                float m0 = macc[nf][col];          // tile wm*16+g
                float m1 = macc[nf][2 + col];      // tile wm*16+g+8
                outacc[0][nf][col][0] += c00 * m0;
                outacc[0][nf][col][1] += c01 * m0;
                outacc[0][nf][col][2] += c10 * m0;
                outacc[0][nf][col][3] += c11 * m0;
                outacc[1][nf][col][0] += c00 * m1;
                outacc[1][nf][col][1] += c01 * m1;
                outacc[1][nf][col][2] += c10 * m1;
                outacc[1][nf][col][3] += c11 * m1;
            }
    }

    // ---- Epilogue
    #pragma unroll
    for (int mrh = 0; mrh < 2; mrh++) {
        const int tile = wm * 16 + g + 8 * mrh;   // 0..63
        const int iL = tile >> 5, j = tile & 31;
        const int irow = 2 * ig + iL;
        if (j < TJ_ && irow < TI_) {
            #pragma unroll
            for (int p = 0; p < 2; p++) {
                const int ho = 2 * irow + p;
                #pragma unroll
                for (int q = 0; q < 2; q++) {
                    const int wo = 2 * j + q;
                    float* op = out + (((size_t)b * 62 + ho) * 62 + wo) * COUT_
                                   + nb * 128 + wn * 64 + 2 * tq;
                    #pragma unroll
                    for (int nf = 0; nf < 8; nf++) {
                        float2 bb = *(const float2*)&bbs[wn * 64 + nf * 8 + 2 * tq];
                        float2 v;
                        v.x = outacc[mrh][nf][0][p * 2 + q] + bb.x;
                        v.y = outacc[mrh][nf][1][p * 2 + q] + bb.y;
                        *(float2*)(op + nf * 8) = v;
                    }
                }
            }
        }
    }
}

extern "C" void kernel_launch(void* const* d_in, const int* in_sizes, int n_in,
                              void* d_out, int out_size)
{
    const float* X    = (const float*)d_in[0];
    const float* W    = (const float*)d_in[1];
    const float* bias = (const float*)d_in[2];
    const float* Werr = (const float*)d_in[3];
    const float* Berr = (const float*)d_in[4];
    float* out = (float*)d_out;

    cudaFuncSetAttribute(wino_u_kernel,
                         cudaFuncAttributeMaxDynamicSharedMemorySize, 65536);
    cudaFuncSetAttribute(wino_v_kernel,
                         cudaFuncAttributeMaxDynamicSharedMemorySize, 106496);
    cudaFuncSetAttribute(wino_main_kernel,
                         cudaFuncAttributeMaxDynamicSharedMemorySize, SMEM_MAIN);

    wino_u_kernel<<<dim3(TI_, 4, 64), 256, 65536>>>(X);
    wino_v_kernel<<<dim3(8, 4, 64), 256, 106496>>>(W, Werr);
    wino_main_kernel<<<dim3(2, 16, 64), 256, SMEM_MAIN>>>(bias, Berr, out);
}